// round 1
// baseline (speedup 1.0000x reference)
#include <cuda_runtime.h>

#define BB 2
#define SS 2048
#define DD 1024
#define HH 16
#define HDD 64
#define MROWS (BB*SS)    // 4096
#define NCOLS (HH*HDD)   // 1024

// Scratch (allocation-free rule: __device__ globals)
__device__ float g_q[(size_t)BB*HH*HDD*SS];   // [B,H,HD,S]  (d-major for flash)
__device__ float g_k[(size_t)BB*HH*HDD*SS];   // [B,H,HD,S]
__device__ float g_v[(size_t)BB*HH*SS*HDD];   // [B,H,S,HD]
__device__ float g_o[(size_t)BB*SS*HH*HDD];   // [B,S,H,HD]  (row-major for O-proj)

// ---------------- packed f32x2 helpers (FFMA2: 2 FMAs / instr) ----------------
__device__ __forceinline__ void ffma2(unsigned long long &d,
                                      unsigned long long a,
                                      unsigned long long b) {
    asm("fma.rn.f32x2 %0, %1, %2, %0;" : "+l"(d) : "l"(a), "l"(b));
}
__device__ __forceinline__ void fmul2(unsigned long long &d,
                                      unsigned long long a,
                                      unsigned long long b) {
    asm("mul.rn.f32x2 %0, %1, %2;" : "=l"(d) : "l"(a), "l"(b));
}
__device__ __forceinline__ unsigned long long splat2(float a) {
    unsigned long long r;
    asm("mov.b64 %0, {%1, %1};" : "=l"(r) : "f"(a));
    return r;
}
__device__ __forceinline__ float2 unpk2(unsigned long long v) {
    float2 r;
    asm("mov.b64 {%0, %1}, %2;" : "=f"(r.x), "=f"(r.y) : "l"(v));
    return r;
}

// ---------------- generic 128x128x8 SGEMM, 256 threads, 8x8/thread ----------------
// MODE 0: C layout [B,H,HD,S]   (Q/K, d-major) ; val = (acc + bias) * scale
// MODE 1: C layout [B,H,S,HD]   (V)
// MODE 2: C layout row-major [M, N]            (final output)
template<int MODE>
__global__ void __launch_bounds__(256) sgemm_kernel(
    const float* __restrict__ A, const float* __restrict__ W,
    const float* __restrict__ bias, float* __restrict__ C,
    int Kdim, float scale)
{
    __shared__ __align__(16) float As[8][128];
    __shared__ __align__(16) float Bs[8][128];
    const int tid  = threadIdx.x;
    const int bm   = blockIdx.y << 7;
    const int bn   = blockIdx.x << 7;
    const int arow = tid >> 1;
    const int acol = (tid & 1) << 2;
    const int brow = tid >> 5;
    const int bcol = (tid & 31) << 2;
    const int ty   = tid >> 4, tx = tid & 15;

    unsigned long long acc2[8][4];
#pragma unroll
    for (int i = 0; i < 8; i++)
#pragma unroll
        for (int j = 0; j < 4; j++) acc2[i][j] = 0ull;

    const float* Ap = A + (size_t)(bm + arow) * Kdim + acol;
    const float* Wp = W + (size_t)brow * NCOLS + bn + bcol;

    for (int k0 = 0; k0 < Kdim; k0 += 8) {
        float4 av = *(const float4*)(Ap + k0);
        float4 wv = *(const float4*)(Wp + (size_t)k0 * NCOLS);
        As[acol + 0][arow] = av.x;
        As[acol + 1][arow] = av.y;
        As[acol + 2][arow] = av.z;
        As[acol + 3][arow] = av.w;
        *(float4*)&Bs[brow][bcol] = wv;
        __syncthreads();
#pragma unroll
        for (int k = 0; k < 8; k++) {
            float4 a0 = *(const float4*)&As[k][ty * 8];
            float4 a1 = *(const float4*)&As[k][ty * 8 + 4];
            ulonglong2 b0 = *(const ulonglong2*)&Bs[k][tx * 8];
            ulonglong2 b1 = *(const ulonglong2*)&Bs[k][tx * 8 + 4];
            unsigned long long as2[8];
            as2[0] = splat2(a0.x); as2[1] = splat2(a0.y);
            as2[2] = splat2(a0.z); as2[3] = splat2(a0.w);
            as2[4] = splat2(a1.x); as2[5] = splat2(a1.y);
            as2[6] = splat2(a1.z); as2[7] = splat2(a1.w);
#pragma unroll
            for (int i = 0; i < 8; i++) {
                ffma2(acc2[i][0], as2[i], b0.x);
                ffma2(acc2[i][1], as2[i], b0.y);
                ffma2(acc2[i][2], as2[i], b1.x);
                ffma2(acc2[i][3], as2[i], b1.y);
            }
        }
        __syncthreads();
    }

#pragma unroll
    for (int i = 0; i < 8; i++) {
        int m  = bm + ty * 8 + i;
        int b_ = m >> 11;        // / S (2048)
        int s  = m & 2047;
        float vals[8];
        float2 u;
        u = unpk2(acc2[i][0]); vals[0] = u.x; vals[1] = u.y;
        u = unpk2(acc2[i][1]); vals[2] = u.x; vals[3] = u.y;
        u = unpk2(acc2[i][2]); vals[4] = u.x; vals[5] = u.y;
        u = unpk2(acc2[i][3]); vals[6] = u.x; vals[7] = u.y;
#pragma unroll
        for (int j = 0; j < 8; j++) {
            int n = bn + tx * 8 + j;
            float val = (vals[j] + bias[n]) * scale;
            if (MODE == 0) {
                int h = n >> 6, hd = n & 63;
                C[((size_t)((b_ * HH + h) * HDD + hd)) * SS + s] = val;
            } else if (MODE == 1) {
                int h = n >> 6, hd = n & 63;
                C[((size_t)((b_ * HH + h) * SS + s)) * HDD + hd] = val;
            } else {
                C[(size_t)m * NCOLS + n] = val;
            }
        }
    }
}

// ---------------- flash attention: BQ=128, BK=64, 256 threads ----------------
// Thread (ty,tx), ty=tid/16, tx=tid%16. Score tile rows ty*8+i, cols tx*4+j.
// Q,K in d-major smem; V natural; P staged in smem [r][j].
__global__ void __launch_bounds__(256, 2) flash_kernel(
    const float* __restrict__ gq, const float* __restrict__ gk,
    const float* __restrict__ gv, float* __restrict__ go)
{
    extern __shared__ __align__(16) float sm[];
    float* Qs = sm;                  // [64][128]  Qs[d*128 + r]
    float* Ks = sm + 64 * 128;       // [64][64]   Ks[d*64 + c]
    float* Vs = Ks + 64 * 64;        // [64][64]   Vs[j*64 + d]
    float* Ps = Vs + 64 * 64;        // [128][64]  Ps[r*64 + j]

    const int tid = threadIdx.x;
    const int ty  = tid >> 4, tx = tid & 15;
    const int qt  = blockIdx.x;      // q tile (of 128)
    const int bh  = blockIdx.y;      // b*H + h

    const float* Qg = gq + (size_t)bh * HDD * SS + qt * 128;
    const float* Kg = gk + (size_t)bh * HDD * SS;
    const float* Vg = gv + (size_t)bh * SS * HDD;

    // Load Q tile (d-major, coalesced): 64 rows(d) x 128 cols(r)
#pragma unroll
    for (int it = 0; it < 8; it++) {
        int t  = it * 256 + tid;
        int d  = t >> 5;
        int r4 = (t & 31) << 2;
        *(float4*)&Qs[d * 128 + r4] = *(const float4*)(Qg + (size_t)d * SS + r4);
    }

    float m_i[8], l_i[8];
    unsigned long long acc2[8][2];
#pragma unroll
    for (int i = 0; i < 8; i++) {
        m_i[i] = -1e30f; l_i[i] = 0.0f;
        acc2[i][0] = 0ull; acc2[i][1] = 0ull;
    }
    __syncthreads();

    for (int kt = 0; kt < SS / 64; kt++) {
        const float* Kt = Kg + kt * 64;
        const float* Vt = Vg + (size_t)kt * 64 * HDD;
#pragma unroll
        for (int it = 0; it < 4; it++) {
            int t  = it * 256 + tid;
            int r  = t >> 4;
            int c4 = (t & 15) << 2;
            *(float4*)&Ks[r * 64 + c4] = *(const float4*)(Kt + (size_t)r * SS + c4);
            *(float4*)&Vs[r * 64 + c4] = *(const float4*)(Vt + (size_t)r * HDD + c4);
        }
        __syncthreads();

        // ---- scores: s[r= ty*8+i][c= tx*4+j] = sum_d Q[r][d] K[c][d]
        unsigned long long s2[8][2];
#pragma unroll
        for (int i = 0; i < 8; i++) { s2[i][0] = 0ull; s2[i][1] = 0ull; }
#pragma unroll 8
        for (int d = 0; d < 64; d++) {
            float4 a0 = *(const float4*)&Qs[d * 128 + ty * 8];
            float4 a1 = *(const float4*)&Qs[d * 128 + ty * 8 + 4];
            ulonglong2 kv = *(const ulonglong2*)&Ks[d * 64 + tx * 4];
            unsigned long long as2[8];
            as2[0] = splat2(a0.x); as2[1] = splat2(a0.y);
            as2[2] = splat2(a0.z); as2[3] = splat2(a0.w);
            as2[4] = splat2(a1.x); as2[5] = splat2(a1.y);
            as2[6] = splat2(a1.z); as2[7] = splat2(a1.w);
#pragma unroll
            for (int i = 0; i < 8; i++) {
                ffma2(s2[i][0], as2[i], kv.x);
                ffma2(s2[i][1], as2[i], kv.y);
            }
        }

        // ---- online softmax (row groups of 16 lanes share a row)
#pragma unroll
        for (int i = 0; i < 8; i++) {
            float2 u0 = unpk2(s2[i][0]);
            float2 u1 = unpk2(s2[i][1]);
            float mx = fmaxf(fmaxf(u0.x, u0.y), fmaxf(u1.x, u1.y));
#pragma unroll
            for (int off = 8; off > 0; off >>= 1)
                mx = fmaxf(mx, __shfl_xor_sync(0xffffffffu, mx, off, 16));
            float mnew  = fmaxf(m_i[i], mx);
            float alpha = __expf(m_i[i] - mnew);
            u0.x = __expf(u0.x - mnew);
            u0.y = __expf(u0.y - mnew);
            u1.x = __expf(u1.x - mnew);
            u1.y = __expf(u1.y - mnew);
            float rs = (u0.x + u0.y) + (u1.x + u1.y);
#pragma unroll
            for (int off = 8; off > 0; off >>= 1)
                rs += __shfl_xor_sync(0xffffffffu, rs, off, 16);
            l_i[i] = l_i[i] * alpha + rs;
            m_i[i] = mnew;
            unsigned long long al2 = splat2(alpha);
            fmul2(acc2[i][0], acc2[i][0], al2);
            fmul2(acc2[i][1], acc2[i][1], al2);
            float4 pv = make_float4(u0.x, u0.y, u1.x, u1.y);
            *(float4*)&Ps[(ty * 8 + i) * 64 + tx * 4] = pv;
        }
        __syncthreads();

        // ---- O += P * V : out rows ty*8+i, dims tx*4..tx*4+3
#pragma unroll 4
        for (int jb = 0; jb < 16; jb++) {
            ulonglong2 vv0 = *(const ulonglong2*)&Vs[(jb * 4 + 0) * 64 + tx * 4];
            ulonglong2 vv1 = *(const ulonglong2*)&Vs[(jb * 4 + 1) * 64 + tx * 4];
            ulonglong2 vv2 = *(const ulonglong2*)&Vs[(jb * 4 + 2) * 64 + tx * 4];
            ulonglong2 vv3 = *(const ulonglong2*)&Vs[(jb * 4 + 3) * 64 + tx * 4];
#pragma unroll
            for (int i = 0; i < 8; i++) {
                float4 pv = *(const float4*)&Ps[(ty * 8 + i) * 64 + jb * 4];
                unsigned long long p0 = splat2(pv.x);
                unsigned long long p1 = splat2(pv.y);
                unsigned long long p2 = splat2(pv.z);
                unsigned long long p3 = splat2(pv.w);
                ffma2(acc2[i][0], p0, vv0.x); ffma2(acc2[i][1], p0, vv0.y);
                ffma2(acc2[i][0], p1, vv1.x); ffma2(acc2[i][1], p1, vv1.y);
                ffma2(acc2[i][0], p2, vv2.x); ffma2(acc2[i][1], p2, vv2.y);
                ffma2(acc2[i][0], p3, vv3.x); ffma2(acc2[i][1], p3, vv3.y);
            }
        }
        __syncthreads();
    }

    // ---- epilogue: normalize, write [B,S,H,HD]
    const int b_ = bh >> 4;
    const int h  = bh & 15;
#pragma unroll
    for (int i = 0; i < 8; i++) {
        int r = qt * 128 + ty * 8 + i;
        float inv = 1.0f / l_i[i];
        float2 o0 = unpk2(acc2[i][0]);
        float2 o1 = unpk2(acc2[i][1]);
        float4 o = make_float4(o0.x * inv, o0.y * inv, o1.x * inv, o1.y * inv);
        *(float4*)&go[((size_t)(b_ * SS + r) * HH + h) * HDD + tx * 4] = o;
    }
}

// ---------------------------------------------------------------------------
extern "C" void kernel_launch(void* const* d_in, const int* in_sizes, int n_in,
                              void* d_out, int out_size)
{
    const float* x  = (const float*)d_in[0];
    const float* wq = (const float*)d_in[1];
    const float* bq = (const float*)d_in[2];
    const float* wk = (const float*)d_in[3];
    const float* bk = (const float*)d_in[4];
    const float* wv = (const float*)d_in[5];
    const float* bv = (const float*)d_in[6];
    const float* wo = (const float*)d_in[7];
    const float* bo = (const float*)d_in[8];
    float* out = (float*)d_out;

    float *gq, *gk, *gv, *go;
    cudaGetSymbolAddress((void**)&gq, g_q);
    cudaGetSymbolAddress((void**)&gk, g_k);
    cudaGetSymbolAddress((void**)&gv, g_v);
    cudaGetSymbolAddress((void**)&go, g_o);

    const int FLASH_SMEM = (64 * 128 + 64 * 64 + 64 * 64 + 128 * 64) * 4; // 96 KB
    cudaFuncSetAttribute(flash_kernel,
                         cudaFuncAttributeMaxDynamicSharedMemorySize, FLASH_SMEM);

    dim3 gblk(NCOLS / 128, MROWS / 128);   // (8, 32)
    const float qscale = 0.125f;           // 1/sqrt(HD)

    sgemm_kernel<0><<<gblk, 256>>>(x, wq, bq, gq, DD, qscale);
    sgemm_kernel<0><<<gblk, 256>>>(x, wk, bk, gk, DD, 1.0f);
    sgemm_kernel<1><<<gblk, 256>>>(x, wv, bv, gv, DD, 1.0f);

    flash_kernel<<<dim3(SS / 128, BB * HH), 256, FLASH_SMEM>>>(gq, gk, gv, go);

    sgemm_kernel<2><<<gblk, 256>>>(go, wo, bo, out, NCOLS, 1.0f);
}

// round 7
// speedup vs baseline: 1.4664x; 1.4664x over previous
#include <cuda_runtime.h>
#include <cstdint>

#define BB 2
#define SS 2048
#define DD 1024
#define HH 16
#define HDD 64
#define MROWS (BB*SS)    // 4096
#define NCOLS (HH*HDD)   // 1024

// ---------------- scratch (__device__ globals; allocation-free rule) ----------------
__device__ float g_q  [(size_t)MROWS*NCOLS];  // [B,H,S,HD], tf32-rounded, pre-scaled 1/8
__device__ float g_k  [(size_t)MROWS*NCOLS];  // [B,H,S,HD], tf32-rounded
__device__ float g_vhi[(size_t)MROWS*NCOLS];  // [B,H,S,HD] tf32 hi
__device__ float g_vlo[(size_t)MROWS*NCOLS];  // [B,H,S,HD] tf32 lo
__device__ float g_o  [(size_t)MROWS*NCOLS];  // [B,S,H*HD] attention out
__device__ float g_xhi[(size_t)MROWS*DD];
__device__ float g_xlo[(size_t)MROWS*DD];
__device__ float g_ohi[(size_t)MROWS*NCOLS];
__device__ float g_olo[(size_t)MROWS*NCOLS];
__device__ float g_wthi[(size_t)4*DD*NCOLS];  // 4 transposed weights [N,K], tf32 hi
__device__ float g_wtlo[(size_t)4*DD*NCOLS];  // lo

// ---------------- helpers ----------------
__device__ __forceinline__ uint32_t smem_u32(const void* p) {
    uint32_t a;
    asm("{ .reg .u64 t; cvta.to.shared.u64 t, %1; cvt.u32.u64 %0, t; }" : "=r"(a) : "l"(p));
    return a;
}
// cvt.rna.tf32.f32 requires a .b32 destination; bit-cast back to float (exact).
__device__ __forceinline__ float tf32_rna(float v) {
    uint32_t r;
    asm("cvt.rna.tf32.f32 %0, %1;" : "=r"(r) : "f"(v));
    return __uint_as_float(r);
}
__device__ __forceinline__ uint32_t f2b(float v) { return __float_as_uint(v); }

__device__ __forceinline__ void cp16(uint32_t s, const void* g) {
    asm volatile("cp.async.cg.shared.global [%0], [%1], 16;" :: "r"(s), "l"(g));
}
__device__ __forceinline__ void cp_commit() { asm volatile("cp.async.commit_group;"); }
template<int N>
__device__ __forceinline__ void cp_wait() {
    asm volatile("cp.async.wait_group %0;" :: "n"(N) : "memory");
}

// mma.sync m16n8k8 tf32 (sm_80+, valid at compute_100 target)
__device__ __forceinline__ void mma8(float* c, const uint32_t* a, const uint32_t* b) {
    asm volatile(
        "mma.sync.aligned.m16n8k8.row.col.f32.tf32.tf32.f32 "
        "{%0,%1,%2,%3}, {%4,%5,%6,%7}, {%8,%9}, {%0,%1,%2,%3};"
        : "+f"(c[0]), "+f"(c[1]), "+f"(c[2]), "+f"(c[3])
        : "r"(a[0]), "r"(a[1]), "r"(a[2]), "r"(a[3]), "r"(b[0]), "r"(b[1]));
}

// ---------------- prep kernels ----------------
__global__ void __launch_bounds__(256) split_kernel(const float* __restrict__ in,
                                                    float* __restrict__ hi,
                                                    float* __restrict__ lo, int n4) {
    int i = blockIdx.x * blockDim.x + threadIdx.x;
    if (i < n4) {
        float4 v = ((const float4*)in)[i];
        float4 h, l;
        h.x = tf32_rna(v.x); l.x = tf32_rna(v.x - h.x);
        h.y = tf32_rna(v.y); l.y = tf32_rna(v.y - h.y);
        h.z = tf32_rna(v.z); l.z = tf32_rna(v.z - h.z);
        h.w = tf32_rna(v.w); l.w = tf32_rna(v.w - h.w);
        ((float4*)hi)[i] = h;
        ((float4*)lo)[i] = l;
    }
}

// W [K=1024][N=1024] -> Wt hi/lo [N][K], 4 matrices via blockIdx.z
__global__ void __launch_bounds__(256) transpose_split_kernel(
    const float* __restrict__ w0, const float* __restrict__ w1,
    const float* __restrict__ w2, const float* __restrict__ w3,
    float* __restrict__ hi, float* __restrict__ lo)
{
    __shared__ float t[32][33];
    int z = blockIdx.z;
    const float* W = (z == 0) ? w0 : (z == 1) ? w1 : (z == 2) ? w2 : w3;
    float* H = hi + (size_t)z * DD * NCOLS;
    float* L = lo + (size_t)z * DD * NCOLS;
    int tx = threadIdx.x & 31, ty = threadIdx.x >> 5;
    int n0 = blockIdx.x * 32, k0 = blockIdx.y * 32;
#pragma unroll
    for (int i = 0; i < 4; i++)
        t[ty + i * 8][tx] = W[(size_t)(k0 + ty + i * 8) * NCOLS + n0 + tx];
    __syncthreads();
#pragma unroll
    for (int i = 0; i < 4; i++) {
        float v = t[tx][ty + i * 8];
        float h = tf32_rna(v);
        size_t o = (size_t)(n0 + ty + i * 8) * DD + k0 + tx;
        H[o] = h;
        L[o] = tf32_rna(v - h);
    }
}

// ---------------- split-tf32 3-pass GEMM via mma.sync ----------------
// 128x128 tile, BK=16, 256 threads (8 warps, warp tile 64x32), double-buffered cp.async.
// MODE 0: C=[B,H,S,HD] rounded tf32, val=(acc+bias)*scale   (Q / K)
// MODE 1: V split -> C=hi, C2=lo, layout [B,H,S,HD]
// MODE 2: C row-major [M][N] plain fp32 (final output)
#define PBK 16
#define PSTR 20                  // floats per smem row (80B, 16B-aligned, conflict-free)
#define PTILE (128*PSTR)         // 2560 floats
#define PTILE_B (PTILE*4)        // 10240 bytes
#define GEMM_SMEM (8*PTILE*4)    // 81920 bytes

template<int MODE>
__global__ void __launch_bounds__(256) gemm_tc(
    const float* __restrict__ Ahi, const float* __restrict__ Alo,
    const float* __restrict__ Bhi, const float* __restrict__ Blo,
    const float* __restrict__ bias, float* __restrict__ C, float* __restrict__ C2,
    int Kdim, float scale)
{
    extern __shared__ float smf[];
    float* sAH = smf;
    float* sAL = smf + 2 * PTILE;
    float* sBH = smf + 4 * PTILE;
    float* sBL = smf + 6 * PTILE;
    const uint32_t uAH = smem_u32(sAH), uAL = smem_u32(sAL);
    const uint32_t uBH = smem_u32(sBH), uBL = smem_u32(sBL);

    const int tid = threadIdx.x, lane = tid & 31, wid = tid >> 5;
    const int grp = lane >> 2, qd = lane & 3;
    const int bm = blockIdx.y << 7, bn = blockIdx.x << 7;
    const int wm = (wid >> 2) << 6, wn = (wid & 3) << 5;

    float c[4][4][4];
#pragma unroll
    for (int i = 0; i < 4; i++)
#pragma unroll
        for (int j = 0; j < 4; j++)
#pragma unroll
            for (int r = 0; r < 4; r++) c[i][j][r] = 0.0f;

    const int NKB = Kdim / PBK;

    // stage loader
    auto load_stage = [&](int kb, int st) {
        int koff = kb * PBK;
#pragma unroll
        for (int i = 0; i < 2; i++) {
            int ch = i * 256 + tid;
            int row = ch >> 2, seg = ch & 3;
            size_t gA = (size_t)(bm + row) * Kdim + koff + seg * 4;
            size_t gB = (size_t)(bn + row) * Kdim + koff + seg * 4;
            uint32_t so = st * PTILE_B + row * 80 + seg * 16;
            cp16(uAH + so, Ahi + gA);
            cp16(uAL + so, Alo + gA);
            cp16(uBH + so, Bhi + gB);
            cp16(uBL + so, Blo + gB);
        }
        cp_commit();
    };

    load_stage(0, 0);
    for (int kb = 0; kb < NKB; kb++) {
        int st = kb & 1;
        if (kb + 1 < NKB) { load_stage(kb + 1, st ^ 1); cp_wait<1>(); }
        else               { cp_wait<0>(); }
        __syncthreads();

        const float* AH = sAH + st * PTILE;
        const float* AL = sAL + st * PTILE;
        const float* BH = sBH + st * PTILE;
        const float* BL = sBL + st * PTILE;

#pragma unroll
        for (int ks = 0; ks < 2; ks++) {
            const int kk = ks * 8;
            uint32_t ah[4][4], bh[4][2];
#pragma unroll
            for (int mt = 0; mt < 4; mt++) {
                const float* p = AH + (wm + mt * 16 + grp) * PSTR + kk + qd;
                ah[mt][0] = f2b(p[0]);
                ah[mt][1] = f2b(p[8 * PSTR]);
                ah[mt][2] = f2b(p[4]);
                ah[mt][3] = f2b(p[8 * PSTR + 4]);
            }
#pragma unroll
            for (int nt = 0; nt < 4; nt++) {
                const float* p = BH + (wn + nt * 8 + grp) * PSTR + kk + qd;
                bh[nt][0] = f2b(p[0]);
                bh[nt][1] = f2b(p[4]);
            }
#pragma unroll
            for (int mt = 0; mt < 4; mt++)
#pragma unroll
                for (int nt = 0; nt < 4; nt++) mma8(c[mt][nt], ah[mt], bh[nt]);

            // pass 2: ah * blo
            {
                uint32_t bl[4][2];
#pragma unroll
                for (int nt = 0; nt < 4; nt++) {
                    const float* p = BL + (wn + nt * 8 + grp) * PSTR + kk + qd;
                    bl[nt][0] = f2b(p[0]);
                    bl[nt][1] = f2b(p[4]);
                }
#pragma unroll
                for (int mt = 0; mt < 4; mt++)
#pragma unroll
                    for (int nt = 0; nt < 4; nt++) mma8(c[mt][nt], ah[mt], bl[nt]);
            }
            // pass 3: alo * bh
            {
                uint32_t al[4][4];
#pragma unroll
                for (int mt = 0; mt < 4; mt++) {
                    const float* p = AL + (wm + mt * 16 + grp) * PSTR + kk + qd;
                    al[mt][0] = f2b(p[0]);
                    al[mt][1] = f2b(p[8 * PSTR]);
                    al[mt][2] = f2b(p[4]);
                    al[mt][3] = f2b(p[8 * PSTR + 4]);
                }
#pragma unroll
                for (int mt = 0; mt < 4; mt++)
#pragma unroll
                    for (int nt = 0; nt < 4; nt++) mma8(c[mt][nt], al[mt], bh[nt]);
            }
        }
        __syncthreads();
    }

    // epilogue
#pragma unroll
    for (int mt = 0; mt < 4; mt++) {
#pragma unroll
        for (int nt = 0; nt < 4; nt++) {
            int n = bn + wn + nt * 8 + 2 * qd;
            float b0v = bias[n], b1v = bias[n + 1];
#pragma unroll
            for (int rr = 0; rr < 2; rr++) {
                int m = bm + wm + mt * 16 + grp + rr * 8;
                float v0 = (c[mt][nt][rr * 2 + 0] + b0v) * scale;
                float v1 = (c[mt][nt][rr * 2 + 1] + b1v) * scale;
                int b_ = m >> 11, s = m & 2047;
                if (MODE == 0) {
                    int h = n >> 6, hd = n & 63;
                    float2 o = make_float2(tf32_rna(v0), tf32_rna(v1));
                    *(float2*)&C[((size_t)(b_ * HH + h) * SS + s) * HDD + hd] = o;
                } else if (MODE == 1) {
                    int h = n >> 6, hd = n & 63;
                    float h0 = tf32_rna(v0), h1 = tf32_rna(v1);
                    size_t off = ((size_t)(b_ * HH + h) * SS + s) * HDD + hd;
                    *(float2*)&C[off]  = make_float2(h0, h1);
                    *(float2*)&C2[off] = make_float2(tf32_rna(v0 - h0), tf32_rna(v1 - h1));
                } else {
                    *(float2*)&C[(size_t)m * NCOLS + n] = make_float2(v0, v1);
                }
            }
        }
    }
}

// ---------------- flash attention via mma.sync tf32 ----------------
// BQ=128 rows/block, BK=64 keys/iter, 256 threads (8 warps x 16 rows each).
// QK single-pass tf32 (inputs pre-rounded); PV 2-pass with V hi/lo.
#define QSTR 68
#define KSTR 68
#define VSTR 72
#define PSTR2 68
#define QOFF 0
#define KOFF  (128*QSTR)               // 8704
#define VHOFF (KOFF + 2*64*KSTR)       // 17408
#define VLOFF (VHOFF + 2*64*VSTR)      // 26624
#define POFF  (VLOFF + 2*64*VSTR)      // 35840
#define FLASH_FLOATS (POFF + 128*PSTR2) // 44544
#define FLASH_SMEM (FLASH_FLOATS*4)     // 178176 B

__global__ void __launch_bounds__(256) flash_kernel(
    const float* __restrict__ gq, const float* __restrict__ gk,
    const float* __restrict__ gvh, const float* __restrict__ gvl,
    float* __restrict__ go)
{
    extern __shared__ float smf[];
    const uint32_t sb = smem_u32(smf);

    const int tid = threadIdx.x, lane = tid & 31, wid = tid >> 5;
    const int grp = lane >> 2, qd = lane & 3;
    const int qt = blockIdx.x;
    const int bh = blockIdx.y;

    const float* Qg = gq  + ((size_t)bh * SS + qt * 128) * HDD;
    const float* Kg = gk  + (size_t)bh * SS * HDD;
    const float* Vh = gvh + (size_t)bh * SS * HDD;
    const float* Vl = gvl + (size_t)bh * SS * HDD;

    // Q load (group 0, together with kv stage 0)
#pragma unroll
    for (int i = 0; i < 8; i++) {
        int ch = i * 256 + tid;
        int row = ch >> 4, seg = ch & 15;
        cp16(sb + (QOFF + row * QSTR) * 4 + seg * 16, Qg + row * 64 + seg * 4);
    }
    auto load_kv = [&](int kt, int st) {
#pragma unroll
        for (int i = 0; i < 4; i++) {
            int ch = i * 256 + tid;
            int row = ch >> 4, seg = ch & 15;
            size_t g = (size_t)(kt * 64 + row) * 64 + seg * 4;
            cp16(sb + (KOFF  + st * 64 * KSTR + row * KSTR) * 4 + seg * 16, Kg + g);
            cp16(sb + (VHOFF + st * 64 * VSTR + row * VSTR) * 4 + seg * 16, Vh + g);
            cp16(sb + (VLOFF + st * 64 * VSTR + row * VSTR) * 4 + seg * 16, Vl + g);
        }
        cp_commit();
    };
    load_kv(0, 0);

    float co[8][4];
#pragma unroll
    for (int i = 0; i < 8; i++)
#pragma unroll
        for (int r = 0; r < 4; r++) co[i][r] = 0.0f;
    float m0 = -1e30f, m1 = -1e30f, l0 = 0.0f, l1 = 0.0f;

    const int r0 = wid * 16;
    const float* Qw = smf + QOFF + (r0 + grp) * QSTR + qd;
    float* Pw  = smf + POFF + (r0 + grp) * PSTR2;

    for (int kt = 0; kt < SS / 64; kt++) {
        const int st = kt & 1;
        __syncthreads();   // all warps done with stage st^1 from iter kt-1
        if (kt + 1 < SS / 64) { load_kv(kt + 1, st ^ 1); cp_wait<1>(); }
        else                   { cp_wait<0>(); }
        __syncthreads();

        const float* Kb  = smf + KOFF  + st * 64 * KSTR;
        const float* Vhb = smf + VHOFF + st * 64 * VSTR;
        const float* Vlb = smf + VLOFF + st * 64 * VSTR;

        // ---- S = Q K^T  (tf32 single pass)
        float cs[8][4];
#pragma unroll
        for (int i = 0; i < 8; i++)
#pragma unroll
            for (int r = 0; r < 4; r++) cs[i][r] = 0.0f;
#pragma unroll
        for (int ks = 0; ks < 8; ks++) {
            const int d = ks * 8;
            uint32_t a[4];
            a[0] = f2b(Qw[d]);
            a[1] = f2b(Qw[d + 8 * QSTR]);
            a[2] = f2b(Qw[d + 4]);
            a[3] = f2b(Qw[d + 8 * QSTR + 4]);
#pragma unroll
            for (int nt = 0; nt < 8; nt++) {
                uint32_t b[2];
                const float* p = Kb + (nt * 8 + grp) * KSTR + d + qd;
                b[0] = f2b(p[0]);
                b[1] = f2b(p[4]);
                mma8(cs[nt], a, b);
            }
        }

        // ---- online softmax (rows r0+grp and r0+grp+8)
        float mx0 = -1e30f, mx1 = -1e30f;
#pragma unroll
        for (int nt = 0; nt < 8; nt++) {
            mx0 = fmaxf(mx0, fmaxf(cs[nt][0], cs[nt][1]));
            mx1 = fmaxf(mx1, fmaxf(cs[nt][2], cs[nt][3]));
        }
        mx0 = fmaxf(mx0, __shfl_xor_sync(0xffffffffu, mx0, 1));
        mx0 = fmaxf(mx0, __shfl_xor_sync(0xffffffffu, mx0, 2));
        mx1 = fmaxf(mx1, __shfl_xor_sync(0xffffffffu, mx1, 1));
        mx1 = fmaxf(mx1, __shfl_xor_sync(0xffffffffu, mx1, 2));
        float mn0 = fmaxf(m0, mx0), mn1 = fmaxf(m1, mx1);
        float al0 = __expf(m0 - mn0), al1 = __expf(m1 - mn1);
        float s0 = 0.0f, s1 = 0.0f;
#pragma unroll
        for (int nt = 0; nt < 8; nt++) {
            float p0 = __expf(cs[nt][0] - mn0);
            float p1 = __expf(cs[nt][1] - mn0);
            float p2 = __expf(cs[nt][2] - mn1);
            float p3 = __expf(cs[nt][3] - mn1);
            s0 += p0 + p1;
            s1 += p2 + p3;
            *(float2*)&Pw[nt * 8 + 2 * qd] =
                make_float2(tf32_rna(p0), tf32_rna(p1));
            *(float2*)&Pw[8 * PSTR2 + nt * 8 + 2 * qd] =
                make_float2(tf32_rna(p2), tf32_rna(p3));
        }
        s0 += __shfl_xor_sync(0xffffffffu, s0, 1);
        s0 += __shfl_xor_sync(0xffffffffu, s0, 2);
        s1 += __shfl_xor_sync(0xffffffffu, s1, 1);
        s1 += __shfl_xor_sync(0xffffffffu, s1, 2);
        l0 = l0 * al0 + s0;
        l1 = l1 * al1 + s1;
        m0 = mn0;
        m1 = mn1;
#pragma unroll
        for (int nt = 0; nt < 8; nt++) {
            co[nt][0] *= al0; co[nt][1] *= al0;
            co[nt][2] *= al1; co[nt][3] *= al1;
        }
        __syncwarp();

        // ---- O += P V  (2-pass: V hi + V lo)
        const float* Pr = Pw + qd;
#pragma unroll
        for (int ks = 0; ks < 8; ks++) {
            const int k0 = ks * 8;
            uint32_t a[4];
            a[0] = f2b(Pr[k0]);
            a[1] = f2b(Pr[k0 + 8 * PSTR2]);
            a[2] = f2b(Pr[k0 + 4]);
            a[3] = f2b(Pr[k0 + 4 + 8 * PSTR2]);
#pragma unroll
            for (int nt = 0; nt < 8; nt++) {
                uint32_t b[2];
                const float* ph = Vhb + (k0 + qd) * VSTR + nt * 8 + grp;
                b[0] = f2b(ph[0]);
                b[1] = f2b(ph[4 * VSTR]);
                mma8(co[nt], a, b);
                const float* pl = Vlb + (k0 + qd) * VSTR + nt * 8 + grp;
                b[0] = f2b(pl[0]);
                b[1] = f2b(pl[4 * VSTR]);
                mma8(co[nt], a, b);
            }
        }
        __syncwarp();
    }

    // ---- epilogue: normalize, write [B,S,H,HD]
    const int b_ = bh >> 4;
    const int h  = bh & 15;
    const float inv0 = 1.0f / l0, inv1 = 1.0f / l1;
    const int q0 = qt * 128 + r0 + grp;
#pragma unroll
    for (int nt = 0; nt < 8; nt++) {
        int n = nt * 8 + 2 * qd;
        *(float2*)&go[((size_t)(b_ * SS + q0) * HH + h) * HDD + n] =
            make_float2(co[nt][0] * inv0, co[nt][1] * inv0);
        *(float2*)&go[((size_t)(b_ * SS + q0 + 8) * HH + h) * HDD + n] =
            make_float2(co[nt][2] * inv1, co[nt][3] * inv1);
    }
}

// ---------------------------------------------------------------------------
extern "C" void kernel_launch(void* const* d_in, const int* in_sizes, int n_in,
                              void* d_out, int out_size)
{
    const float* x  = (const float*)d_in[0];
    const float* wq = (const float*)d_in[1];
    const float* bq = (const float*)d_in[2];
    const float* wk = (const float*)d_in[3];
    const float* bk = (const float*)d_in[4];
    const float* wv = (const float*)d_in[5];
    const float* bv = (const float*)d_in[6];
    const float* wo = (const float*)d_in[7];
    const float* bo = (const float*)d_in[8];
    float* out = (float*)d_out;

    float *gq, *gk, *gvh, *gvl, *go, *xhi, *xlo, *ohi, *olo, *wthi, *wtlo;
    cudaGetSymbolAddress((void**)&gq,   g_q);
    cudaGetSymbolAddress((void**)&gk,   g_k);
    cudaGetSymbolAddress((void**)&gvh,  g_vhi);
    cudaGetSymbolAddress((void**)&gvl,  g_vlo);
    cudaGetSymbolAddress((void**)&go,   g_o);
    cudaGetSymbolAddress((void**)&xhi,  g_xhi);
    cudaGetSymbolAddress((void**)&xlo,  g_xlo);
    cudaGetSymbolAddress((void**)&ohi,  g_ohi);
    cudaGetSymbolAddress((void**)&olo,  g_olo);
    cudaGetSymbolAddress((void**)&wthi, g_wthi);
    cudaGetSymbolAddress((void**)&wtlo, g_wtlo);

    cudaFuncSetAttribute(gemm_tc<0>, cudaFuncAttributeMaxDynamicSharedMemorySize, GEMM_SMEM);
    cudaFuncSetAttribute(gemm_tc<1>, cudaFuncAttributeMaxDynamicSharedMemorySize, GEMM_SMEM);
    cudaFuncSetAttribute(gemm_tc<2>, cudaFuncAttributeMaxDynamicSharedMemorySize, GEMM_SMEM);
    cudaFuncSetAttribute(flash_kernel, cudaFuncAttributeMaxDynamicSharedMemorySize, FLASH_SMEM);

    // prep
    split_kernel<<<(MROWS * DD / 4 + 255) / 256, 256>>>(x, xhi, xlo, MROWS * DD / 4);
    transpose_split_kernel<<<dim3(NCOLS / 32, DD / 32, 4), 256>>>(wq, wk, wv, wo, wthi, wtlo);

    dim3 gblk(NCOLS / 128, MROWS / 128);   // (8, 32)
    const size_t WSZ = (size_t)DD * NCOLS;

    gemm_tc<0><<<gblk, 256, GEMM_SMEM>>>(xhi, xlo, wthi + 0 * WSZ, wtlo + 0 * WSZ,
                                         bq, gq, nullptr, DD, 0.125f);
    gemm_tc<0><<<gblk, 256, GEMM_SMEM>>>(xhi, xlo, wthi + 1 * WSZ, wtlo + 1 * WSZ,
                                         bk, gk, nullptr, DD, 1.0f);
    gemm_tc<1><<<gblk, 256, GEMM_SMEM>>>(xhi, xlo, wthi + 2 * WSZ, wtlo + 2 * WSZ,
                                         bv, gvh, gvl, DD, 1.0f);

    flash_kernel<<<dim3(SS / 128, BB * HH), 256, FLASH_SMEM>>>(gq, gk, gvh, gvl, go);

    split_kernel<<<(MROWS * NCOLS / 4 + 255) / 256, 256>>>(go, ohi, olo, MROWS * NCOLS / 4);
    gemm_tc<2><<<gblk, 256, GEMM_SMEM>>>(ohi, olo, wthi + 3 * WSZ, wtlo + 3 * WSZ,
                                         bo, out, nullptr, NCOLS, 1.0f);
}

// round 8
// speedup vs baseline: 2.0950x; 1.4287x over previous
#include <cuda_runtime.h>
#include <cuda_bf16.h>
#include <cstdint>

#define BB 2
#define SS 2048
#define DD 1024
#define HH 16
#define HDD 64
#define MROWS (BB*SS)    // 4096
#define NCOLS (HH*HDD)   // 1024

// ---------------- scratch (__device__ globals; allocation-free rule) ----------------
__device__ float g_q  [(size_t)MROWS*NCOLS];  // [B,H,S,HD], tf32-rounded, pre-scaled 1/8
__device__ float g_k  [(size_t)MROWS*NCOLS];  // [B,H,S,HD], tf32-rounded
__device__ float g_vhi[(size_t)MROWS*NCOLS];  // [B,H,S,HD] tf32 hi (flash PV operand)
__device__ float g_vlo[(size_t)MROWS*NCOLS];  // [B,H,S,HD] tf32 lo
__device__ float g_o  [(size_t)MROWS*NCOLS];  // [B,S,H*HD] attention out
__device__ __nv_bfloat16 g_xhi[(size_t)MROWS*DD];    // x split, bf16
__device__ __nv_bfloat16 g_xlo[(size_t)MROWS*DD];
__device__ __nv_bfloat16 g_ohi[(size_t)MROWS*NCOLS]; // attn-out split, bf16
__device__ __nv_bfloat16 g_olo[(size_t)MROWS*NCOLS];
__device__ __nv_bfloat16 g_wthi[(size_t)4*DD*NCOLS]; // 4 transposed weights [N,K], bf16 hi
__device__ __nv_bfloat16 g_wtlo[(size_t)4*DD*NCOLS]; // lo

// ---------------- helpers ----------------
__device__ __forceinline__ uint32_t smem_u32(const void* p) {
    uint32_t a;
    asm("{ .reg .u64 t; cvta.to.shared.u64 t, %1; cvt.u32.u64 %0, t; }" : "=r"(a) : "l"(p));
    return a;
}
// cvt.rna.tf32.f32 requires a .b32 destination; bit-cast back to float (exact).
__device__ __forceinline__ float tf32_rna(float v) {
    uint32_t r;
    asm("cvt.rna.tf32.f32 %0, %1;" : "=r"(r) : "f"(v));
    return __uint_as_float(r);
}
__device__ __forceinline__ uint32_t f2b(float v) { return __float_as_uint(v); }

__device__ __forceinline__ void cp16(uint32_t s, const void* g) {
    asm volatile("cp.async.cg.shared.global [%0], [%1], 16;" :: "r"(s), "l"(g));
}
__device__ __forceinline__ void cp_commit() { asm volatile("cp.async.commit_group;"); }
template<int N>
__device__ __forceinline__ void cp_wait() {
    asm volatile("cp.async.wait_group %0;" :: "n"(N) : "memory");
}

// mma.sync m16n8k8 tf32 (flash kernel)
__device__ __forceinline__ void mma8(float* c, const uint32_t* a, const uint32_t* b) {
    asm volatile(
        "mma.sync.aligned.m16n8k8.row.col.f32.tf32.tf32.f32 "
        "{%0,%1,%2,%3}, {%4,%5,%6,%7}, {%8,%9}, {%0,%1,%2,%3};"
        : "+f"(c[0]), "+f"(c[1]), "+f"(c[2]), "+f"(c[3])
        : "r"(a[0]), "r"(a[1]), "r"(a[2]), "r"(a[3]), "r"(b[0]), "r"(b[1]));
}
// mma.sync m16n8k16 bf16 (projection GEMMs)
__device__ __forceinline__ void mma16(float* c, const uint32_t* a, const uint32_t* b) {
    asm volatile(
        "mma.sync.aligned.m16n8k16.row.col.f32.bf16.bf16.f32 "
        "{%0,%1,%2,%3}, {%4,%5,%6,%7}, {%8,%9}, {%0,%1,%2,%3};"
        : "+f"(c[0]), "+f"(c[1]), "+f"(c[2]), "+f"(c[3])
        : "r"(a[0]), "r"(a[1]), "r"(a[2]), "r"(a[3]), "r"(b[0]), "r"(b[1]));
}

__device__ __forceinline__ void bf16_split(float v, __nv_bfloat16& h, __nv_bfloat16& l) {
    h = __float2bfloat16(v);
    l = __float2bfloat16(v - __bfloat162float(h));
}

// ---------------- prep kernels ----------------
struct alignas(8) bf16x4 { __nv_bfloat162 a, b; };

__global__ void __launch_bounds__(256) split_kernel(const float* __restrict__ in,
                                                    __nv_bfloat16* __restrict__ hi,
                                                    __nv_bfloat16* __restrict__ lo, int n4) {
    int i = blockIdx.x * blockDim.x + threadIdx.x;
    if (i < n4) {
        float4 v = ((const float4*)in)[i];
        __nv_bfloat16 h0, h1, h2, h3, l0, l1, l2, l3;
        bf16_split(v.x, h0, l0);
        bf16_split(v.y, h1, l1);
        bf16_split(v.z, h2, l2);
        bf16_split(v.w, h3, l3);
        bf16x4 H; H.a = __nv_bfloat162(h0, h1); H.b = __nv_bfloat162(h2, h3);
        bf16x4 L; L.a = __nv_bfloat162(l0, l1); L.b = __nv_bfloat162(l2, l3);
        ((bf16x4*)hi)[i] = H;
        ((bf16x4*)lo)[i] = L;
    }
}

// W [K=1024][N=1024] -> Wt hi/lo [N][K] bf16, 4 matrices via blockIdx.z
__global__ void __launch_bounds__(256) transpose_split_kernel(
    const float* __restrict__ w0, const float* __restrict__ w1,
    const float* __restrict__ w2, const float* __restrict__ w3,
    __nv_bfloat16* __restrict__ hi, __nv_bfloat16* __restrict__ lo)
{
    __shared__ float t[32][33];
    int z = blockIdx.z;
    const float* W = (z == 0) ? w0 : (z == 1) ? w1 : (z == 2) ? w2 : w3;
    __nv_bfloat16* H = hi + (size_t)z * DD * NCOLS;
    __nv_bfloat16* L = lo + (size_t)z * DD * NCOLS;
    int tx = threadIdx.x & 31, ty = threadIdx.x >> 5;
    int n0 = blockIdx.x * 32, k0 = blockIdx.y * 32;
#pragma unroll
    for (int i = 0; i < 4; i++)
        t[ty + i * 8][tx] = W[(size_t)(k0 + ty + i * 8) * NCOLS + n0 + tx];
    __syncthreads();
#pragma unroll
    for (int i = 0; i < 4; i++) {
        float v = t[tx][ty + i * 8];
        __nv_bfloat16 h, l;
        bf16_split(v, h, l);
        size_t o = (size_t)(n0 + ty + i * 8) * DD + k0 + tx;
        H[o] = h;
        L[o] = l;
    }
}

// ---------------- bf16x3 GEMM via mma.sync m16n8k16 ----------------
// 128x128 tile, BK=32, 256 threads (8 warps, warp tile 64x32), double-buffered cp.async.
// D = Ah*Bh + Ah*Bl + Al*Bh  (per-product err ~2^-18)
// MODE 0: C=[B,H,S,HD] rounded tf32, val=(acc+bias)*scale   (Q / K)
// MODE 1: V split -> C=hi(f32 tf32), C2=lo, layout [B,H,S,HD]
// MODE 2: C row-major [M][N] plain fp32 (final output)
#define BK2 32
#define BSTRW 20                  // 32-bit words per smem row (40 bf16; conflict-free)
#define BTILE_W (128*BSTRW)       // 2560 words = 10240 bytes per tile
#define GEMM_SMEM (8*BTILE_W*4)   // 81920 bytes

template<int MODE>
__global__ void __launch_bounds__(256) gemm_tc(
    const __nv_bfloat16* __restrict__ Ahi, const __nv_bfloat16* __restrict__ Alo,
    const __nv_bfloat16* __restrict__ Bhi, const __nv_bfloat16* __restrict__ Blo,
    const float* __restrict__ bias, float* __restrict__ C, float* __restrict__ C2,
    int Kdim, float scale)
{
    extern __shared__ uint32_t smw[];
    uint32_t* sAH = smw;
    uint32_t* sAL = smw + 2 * BTILE_W;
    uint32_t* sBH = smw + 4 * BTILE_W;
    uint32_t* sBL = smw + 6 * BTILE_W;
    const uint32_t uAH = smem_u32(sAH), uAL = smem_u32(sAL);
    const uint32_t uBH = smem_u32(sBH), uBL = smem_u32(sBL);

    const int tid = threadIdx.x, lane = tid & 31, wid = tid >> 5;
    const int grp = lane >> 2, qd = lane & 3;
    const int bm = blockIdx.y << 7, bn = blockIdx.x << 7;
    const int wm = (wid >> 2) << 6, wn = (wid & 3) << 5;

    float c[4][4][4];
#pragma unroll
    for (int i = 0; i < 4; i++)
#pragma unroll
        for (int j = 0; j < 4; j++)
#pragma unroll
            for (int r = 0; r < 4; r++) c[i][j][r] = 0.0f;

    const int NKB = Kdim / BK2;

    // stage loader: 4 tiles of 128 rows x 32 bf16 (64B/row = 4 x cp16)
    auto load_stage = [&](int kb, int st) {
        int koff = kb * BK2;
#pragma unroll
        for (int i = 0; i < 2; i++) {
            int ch = i * 256 + tid;          // 0..511
            int row = ch >> 2, cseg = ch & 3;
            size_t gA = (size_t)(bm + row) * Kdim + koff + cseg * 8;
            size_t gB = (size_t)(bn + row) * Kdim + koff + cseg * 8;
            uint32_t so = (st * BTILE_W + row * BSTRW + cseg * 4) * 4;
            cp16(uAH + so, Ahi + gA);
            cp16(uAL + so, Alo + gA);
            cp16(uBH + so, Bhi + gB);
            cp16(uBL + so, Blo + gB);
        }
        cp_commit();
    };

    load_stage(0, 0);
    for (int kb = 0; kb < NKB; kb++) {
        int st = kb & 1;
        if (kb + 1 < NKB) { load_stage(kb + 1, st ^ 1); cp_wait<1>(); }
        else               { cp_wait<0>(); }
        __syncthreads();

        const uint32_t* AH = sAH + st * BTILE_W;
        const uint32_t* AL = sAL + st * BTILE_W;
        const uint32_t* BH = sBH + st * BTILE_W;
        const uint32_t* BL = sBL + st * BTILE_W;

#pragma unroll
        for (int ks = 0; ks < 2; ks++) {           // two k16 steps per BK=32
            const int kw = ks * 8 + qd;            // word offset of k-pair qd
            uint32_t ah[4][4], bh[4][2];
#pragma unroll
            for (int mt = 0; mt < 4; mt++) {
                const uint32_t* p = AH + (wm + mt * 16 + grp) * BSTRW + kw;
                ah[mt][0] = p[0];
                ah[mt][1] = p[8 * BSTRW];
                ah[mt][2] = p[4];
                ah[mt][3] = p[8 * BSTRW + 4];
            }
#pragma unroll
            for (int nt = 0; nt < 4; nt++) {
                const uint32_t* p = BH + (wn + nt * 8 + grp) * BSTRW + kw;
                bh[nt][0] = p[0];
                bh[nt][1] = p[4];
            }
#pragma unroll
            for (int mt = 0; mt < 4; mt++)
#pragma unroll
                for (int nt = 0; nt < 4; nt++) mma16(c[mt][nt], ah[mt], bh[nt]);

            // pass 2: ah * bl
            {
                uint32_t bl[4][2];
#pragma unroll
                for (int nt = 0; nt < 4; nt++) {
                    const uint32_t* p = BL + (wn + nt * 8 + grp) * BSTRW + kw;
                    bl[nt][0] = p[0];
                    bl[nt][1] = p[4];
                }
#pragma unroll
                for (int mt = 0; mt < 4; mt++)
#pragma unroll
                    for (int nt = 0; nt < 4; nt++) mma16(c[mt][nt], ah[mt], bl[nt]);
            }
            // pass 3: al * bh
            {
                uint32_t al[4][4];
#pragma unroll
                for (int mt = 0; mt < 4; mt++) {
                    const uint32_t* p = AL + (wm + mt * 16 + grp) * BSTRW + kw;
                    al[mt][0] = p[0];
                    al[mt][1] = p[8 * BSTRW];
                    al[mt][2] = p[4];
                    al[mt][3] = p[8 * BSTRW + 4];
                }
#pragma unroll
                for (int mt = 0; mt < 4; mt++)
#pragma unroll
                    for (int nt = 0; nt < 4; nt++) mma16(c[mt][nt], al[mt], bh[nt]);
            }
        }
        __syncthreads();
    }

    // epilogue (identical to R7)
#pragma unroll
    for (int mt = 0; mt < 4; mt++) {
#pragma unroll
        for (int nt = 0; nt < 4; nt++) {
            int n = bn + wn + nt * 8 + 2 * qd;
            float b0v = bias[n], b1v = bias[n + 1];
#pragma unroll
            for (int rr = 0; rr < 2; rr++) {
                int m = bm + wm + mt * 16 + grp + rr * 8;
                float v0 = (c[mt][nt][rr * 2 + 0] + b0v) * scale;
                float v1 = (c[mt][nt][rr * 2 + 1] + b1v) * scale;
                int b_ = m >> 11, s = m & 2047;
                if (MODE == 0) {
                    int h = n >> 6, hd = n & 63;
                    float2 o = make_float2(tf32_rna(v0), tf32_rna(v1));
                    *(float2*)&C[((size_t)(b_ * HH + h) * SS + s) * HDD + hd] = o;
                } else if (MODE == 1) {
                    int h = n >> 6, hd = n & 63;
                    float h0 = tf32_rna(v0), h1 = tf32_rna(v1);
                    size_t off = ((size_t)(b_ * HH + h) * SS + s) * HDD + hd;
                    *(float2*)&C[off]  = make_float2(h0, h1);
                    *(float2*)&C2[off] = make_float2(tf32_rna(v0 - h0), tf32_rna(v1 - h1));
                } else {
                    *(float2*)&C[(size_t)m * NCOLS + n] = make_float2(v0, v1);
                }
            }
        }
    }
}

// ---------------- flash attention via mma.sync tf32 (unchanged from R7) ----------------
#define QSTR 68
#define KSTR 68
#define VSTR 72
#define PSTR2 68
#define QOFF 0
#define KOFF  (128*QSTR)               // 8704
#define VHOFF (KOFF + 2*64*KSTR)       // 17408
#define VLOFF (VHOFF + 2*64*VSTR)      // 26624
#define POFF  (VLOFF + 2*64*VSTR)      // 35840
#define FLASH_FLOATS (POFF + 128*PSTR2) // 44544
#define FLASH_SMEM (FLASH_FLOATS*4)     // 178176 B

__global__ void __launch_bounds__(256) flash_kernel(
    const float* __restrict__ gq, const float* __restrict__ gk,
    const float* __restrict__ gvh, const float* __restrict__ gvl,
    float* __restrict__ go)
{
    extern __shared__ float smf[];
    const uint32_t sb = smem_u32(smf);

    const int tid = threadIdx.x, lane = tid & 31, wid = tid >> 5;
    const int grp = lane >> 2, qd = lane & 3;
    const int qt = blockIdx.x;
    const int bh = blockIdx.y;

    const float* Qg = gq  + ((size_t)bh * SS + qt * 128) * HDD;
    const float* Kg = gk  + (size_t)bh * SS * HDD;
    const float* Vh = gvh + (size_t)bh * SS * HDD;
    const float* Vl = gvl + (size_t)bh * SS * HDD;

#pragma unroll
    for (int i = 0; i < 8; i++) {
        int ch = i * 256 + tid;
        int row = ch >> 4, seg = ch & 15;
        cp16(sb + (QOFF + row * QSTR) * 4 + seg * 16, Qg + row * 64 + seg * 4);
    }
    auto load_kv = [&](int kt, int st) {
#pragma unroll
        for (int i = 0; i < 4; i++) {
            int ch = i * 256 + tid;
            int row = ch >> 4, seg = ch & 15;
            size_t g = (size_t)(kt * 64 + row) * 64 + seg * 4;
            cp16(sb + (KOFF  + st * 64 * KSTR + row * KSTR) * 4 + seg * 16, Kg + g);
            cp16(sb + (VHOFF + st * 64 * VSTR + row * VSTR) * 4 + seg * 16, Vh + g);
            cp16(sb + (VLOFF + st * 64 * VSTR + row * VSTR) * 4 + seg * 16, Vl + g);
        }
        cp_commit();
    };
    load_kv(0, 0);

    float co[8][4];
#pragma unroll
    for (int i = 0; i < 8; i++)
#pragma unroll
        for (int r = 0; r < 4; r++) co[i][r] = 0.0f;
    float m0 = -1e30f, m1 = -1e30f, l0 = 0.0f, l1 = 0.0f;

    const int r0 = wid * 16;
    const float* Qw = smf + QOFF + (r0 + grp) * QSTR + qd;
    float* Pw  = smf + POFF + (r0 + grp) * PSTR2;

    for (int kt = 0; kt < SS / 64; kt++) {
        const int st = kt & 1;
        __syncthreads();
        if (kt + 1 < SS / 64) { load_kv(kt + 1, st ^ 1); cp_wait<1>(); }
        else                   { cp_wait<0>(); }
        __syncthreads();

        const float* Kb  = smf + KOFF  + st * 64 * KSTR;
        const float* Vhb = smf + VHOFF + st * 64 * VSTR;
        const float* Vlb = smf + VLOFF + st * 64 * VSTR;

        float cs[8][4];
#pragma unroll
        for (int i = 0; i < 8; i++)
#pragma unroll
            for (int r = 0; r < 4; r++) cs[i][r] = 0.0f;
#pragma unroll
        for (int ks = 0; ks < 8; ks++) {
            const int d = ks * 8;
            uint32_t a[4];
            a[0] = f2b(Qw[d]);
            a[1] = f2b(Qw[d + 8 * QSTR]);
            a[2] = f2b(Qw[d + 4]);
            a[3] = f2b(Qw[d + 8 * QSTR + 4]);
#pragma unroll
            for (int nt = 0; nt < 8; nt++) {
                uint32_t b[2];
                const float* p = Kb + (nt * 8 + grp) * KSTR + d + qd;
                b[0] = f2b(p[0]);
                b[1] = f2b(p[4]);
                mma8(cs[nt], a, b);
            }
        }

        float mx0 = -1e30f, mx1 = -1e30f;
#pragma unroll
        for (int nt = 0; nt < 8; nt++) {
            mx0 = fmaxf(mx0, fmaxf(cs[nt][0], cs[nt][1]));
            mx1 = fmaxf(mx1, fmaxf(cs[nt][2], cs[nt][3]));
        }
        mx0 = fmaxf(mx0, __shfl_xor_sync(0xffffffffu, mx0, 1));
        mx0 = fmaxf(mx0, __shfl_xor_sync(0xffffffffu, mx0, 2));
        mx1 = fmaxf(mx1, __shfl_xor_sync(0xffffffffu, mx1, 1));
        mx1 = fmaxf(mx1, __shfl_xor_sync(0xffffffffu, mx1, 2));
        float mn0 = fmaxf(m0, mx0), mn1 = fmaxf(m1, mx1);
        float al0 = __expf(m0 - mn0), al1 = __expf(m1 - mn1);
        float s0 = 0.0f, s1 = 0.0f;
#pragma unroll
        for (int nt = 0; nt < 8; nt++) {
            float p0 = __expf(cs[nt][0] - mn0);
            float p1 = __expf(cs[nt][1] - mn0);
            float p2 = __expf(cs[nt][2] - mn1);
            float p3 = __expf(cs[nt][3] - mn1);
            s0 += p0 + p1;
            s1 += p2 + p3;
            *(float2*)&Pw[nt * 8 + 2 * qd] =
                make_float2(tf32_rna(p0), tf32_rna(p1));
            *(float2*)&Pw[8 * PSTR2 + nt * 8 + 2 * qd] =
                make_float2(tf32_rna(p2), tf32_rna(p3));
        }
        s0 += __shfl_xor_sync(0xffffffffu, s0, 1);
        s0 += __shfl_xor_sync(0xffffffffu, s0, 2);
        s1 += __shfl_xor_sync(0xffffffffu, s1, 1);
        s1 += __shfl_xor_sync(0xffffffffu, s1, 2);
        l0 = l0 * al0 + s0;
        l1 = l1 * al1 + s1;
        m0 = mn0;
        m1 = mn1;
#pragma unroll
        for (int nt = 0; nt < 8; nt++) {
            co[nt][0] *= al0; co[nt][1] *= al0;
            co[nt][2] *= al1; co[nt][3] *= al1;
        }
        __syncwarp();

        const float* Pr = Pw + qd;
#pragma unroll
        for (int ks = 0; ks < 8; ks++) {
            const int k0 = ks * 8;
            uint32_t a[4];
            a[0] = f2b(Pr[k0]);
            a[1] = f2b(Pr[k0 + 8 * PSTR2]);
            a[2] = f2b(Pr[k0 + 4]);
            a[3] = f2b(Pr[k0 + 4 + 8 * PSTR2]);
#pragma unroll
            for (int nt = 0; nt < 8; nt++) {
                uint32_t b[2];
                const float* ph = Vhb + (k0 + qd) * VSTR + nt * 8 + grp;
                b[0] = f2b(ph[0]);
                b[1] = f2b(ph[4 * VSTR]);
                mma8(co[nt], a, b);
                const float* pl = Vlb + (k0 + qd) * VSTR + nt * 8 + grp;
                b[0] = f2b(pl[0]);
                b[1] = f2b(pl[4 * VSTR]);
                mma8(co[nt], a, b);
            }
        }
        __syncwarp();
    }

    const int b_ = bh >> 4;
    const int h  = bh & 15;
    const float inv0 = 1.0f / l0, inv1 = 1.0f / l1;
    const int q0 = qt * 128 + r0 + grp;
#pragma unroll
    for (int nt = 0; nt < 8; nt++) {
        int n = nt * 8 + 2 * qd;
        *(float2*)&go[((size_t)(b_ * SS + q0) * HH + h) * HDD + n] =
            make_float2(co[nt][0] * inv0, co[nt][1] * inv0);
        *(float2*)&go[((size_t)(b_ * SS + q0 + 8) * HH + h) * HDD + n] =
            make_float2(co[nt][2] * inv1, co[nt][3] * inv1);
    }
}

// ---------------------------------------------------------------------------
extern "C" void kernel_launch(void* const* d_in, const int* in_sizes, int n_in,
                              void* d_out, int out_size)
{
    const float* x  = (const float*)d_in[0];
    const float* wq = (const float*)d_in[1];
    const float* bq = (const float*)d_in[2];
    const float* wk = (const float*)d_in[3];
    const float* bk = (const float*)d_in[4];
    const float* wv = (const float*)d_in[5];
    const float* bv = (const float*)d_in[6];
    const float* wo = (const float*)d_in[7];
    const float* bo = (const float*)d_in[8];
    float* out = (float*)d_out;

    float *gq, *gk, *gvh, *gvl, *go;
    __nv_bfloat16 *xhi, *xlo, *ohi, *olo, *wthi, *wtlo;
    cudaGetSymbolAddress((void**)&gq,   g_q);
    cudaGetSymbolAddress((void**)&gk,   g_k);
    cudaGetSymbolAddress((void**)&gvh,  g_vhi);
    cudaGetSymbolAddress((void**)&gvl,  g_vlo);
    cudaGetSymbolAddress((void**)&go,   g_o);
    cudaGetSymbolAddress((void**)&xhi,  g_xhi);
    cudaGetSymbolAddress((void**)&xlo,  g_xlo);
    cudaGetSymbolAddress((void**)&ohi,  g_ohi);
    cudaGetSymbolAddress((void**)&olo,  g_olo);
    cudaGetSymbolAddress((void**)&wthi, g_wthi);
    cudaGetSymbolAddress((void**)&wtlo, g_wtlo);

    cudaFuncSetAttribute(gemm_tc<0>, cudaFuncAttributeMaxDynamicSharedMemorySize, GEMM_SMEM);
    cudaFuncSetAttribute(gemm_tc<1>, cudaFuncAttributeMaxDynamicSharedMemorySize, GEMM_SMEM);
    cudaFuncSetAttribute(gemm_tc<2>, cudaFuncAttributeMaxDynamicSharedMemorySize, GEMM_SMEM);
    cudaFuncSetAttribute(flash_kernel, cudaFuncAttributeMaxDynamicSharedMemorySize, FLASH_SMEM);

    // prep
    split_kernel<<<(MROWS * DD / 4 + 255) / 256, 256>>>(x, xhi, xlo, MROWS * DD / 4);
    transpose_split_kernel<<<dim3(NCOLS / 32, DD / 32, 4), 256>>>(wq, wk, wv, wo, wthi, wtlo);

    dim3 gblk(NCOLS / 128, MROWS / 128);   // (8, 32)
    const size_t WSZ = (size_t)DD * NCOLS;

    gemm_tc<0><<<gblk, 256, GEMM_SMEM>>>(xhi, xlo, wthi + 0 * WSZ, wtlo + 0 * WSZ,
                                         bq, gq, nullptr, DD, 0.125f);
    gemm_tc<0><<<gblk, 256, GEMM_SMEM>>>(xhi, xlo, wthi + 1 * WSZ, wtlo + 1 * WSZ,
                                         bk, gk, nullptr, DD, 1.0f);
    gemm_tc<1><<<gblk, 256, GEMM_SMEM>>>(xhi, xlo, wthi + 2 * WSZ, wtlo + 2 * WSZ,
                                         bv, gvh, gvl, DD, 1.0f);

    flash_kernel<<<dim3(SS / 128, BB * HH), 256, FLASH_SMEM>>>(gq, gk, gvh, gvl, go);

    split_kernel<<<(MROWS * NCOLS / 4 + 255) / 256, 256>>>(go, ohi, olo, MROWS * NCOLS / 4);
    gemm_tc<2><<<gblk, 256, GEMM_SMEM>>>(ohi, olo, wthi + 3 * WSZ, wtlo + 3 * WSZ,
                                         bo, out, nullptr, NCOLS, 1.0f);
}

// round 9
// speedup vs baseline: 2.1049x; 1.0047x over previous
#include <cuda_runtime.h>
#include <cuda_bf16.h>
#include <cstdint>

#define BB 2
#define SS 2048
#define DD 1024
#define HH 16
#define HDD 64
#define MROWS (BB*SS)    // 4096
#define NCOLS (HH*HDD)   // 1024

// ---------------- scratch (__device__ globals; allocation-free rule) ----------------
__device__ float g_q  [(size_t)MROWS*NCOLS];  // [B,H,S,HD], tf32-rounded, pre-scaled 1/8
__device__ float g_k  [(size_t)MROWS*NCOLS];  // [B,H,S,HD], tf32-rounded
__device__ __nv_bfloat16 g_vhi[(size_t)MROWS*NCOLS]; // V^T [B,H,HD,S] bf16 hi
__device__ __nv_bfloat16 g_vlo[(size_t)MROWS*NCOLS]; // V^T bf16 lo
__device__ float g_o  [(size_t)MROWS*NCOLS];  // [B,S,H*HD] attention out
__device__ __nv_bfloat16 g_xhi[(size_t)MROWS*DD];    // x split, bf16
__device__ __nv_bfloat16 g_xlo[(size_t)MROWS*DD];
__device__ __nv_bfloat16 g_ohi[(size_t)MROWS*NCOLS]; // attn-out split, bf16
__device__ __nv_bfloat16 g_olo[(size_t)MROWS*NCOLS];
__device__ __nv_bfloat16 g_wthi[(size_t)4*DD*NCOLS]; // 4 transposed weights [N,K], bf16 hi
__device__ __nv_bfloat16 g_wtlo[(size_t)4*DD*NCOLS]; // lo

// ---------------- helpers ----------------
__device__ __forceinline__ uint32_t smem_u32(const void* p) {
    uint32_t a;
    asm("{ .reg .u64 t; cvta.to.shared.u64 t, %1; cvt.u32.u64 %0, t; }" : "=r"(a) : "l"(p));
    return a;
}
__device__ __forceinline__ float tf32_rna(float v) {
    uint32_t r;
    asm("cvt.rna.tf32.f32 %0, %1;" : "=r"(r) : "f"(v));
    return __uint_as_float(r);
}
__device__ __forceinline__ uint32_t f2b(float v) { return __float_as_uint(v); }
// pack two f32 -> bf16x2 word, lo in bits[15:0]
__device__ __forceinline__ uint32_t pack_bf16(float lo, float hi) {
    uint32_t r;
    asm("cvt.rn.bf16x2.f32 %0, %1, %2;" : "=r"(r) : "f"(hi), "f"(lo));
    return r;
}

__device__ __forceinline__ void cp16(uint32_t s, const void* g) {
    asm volatile("cp.async.cg.shared.global [%0], [%1], 16;" :: "r"(s), "l"(g));
}
__device__ __forceinline__ void cp_commit() { asm volatile("cp.async.commit_group;"); }
template<int N>
__device__ __forceinline__ void cp_wait() {
    asm volatile("cp.async.wait_group %0;" :: "n"(N) : "memory");
}

// mma.sync m16n8k8 tf32 (flash QK)
__device__ __forceinline__ void mma8(float* c, const uint32_t* a, const uint32_t* b) {
    asm volatile(
        "mma.sync.aligned.m16n8k8.row.col.f32.tf32.tf32.f32 "
        "{%0,%1,%2,%3}, {%4,%5,%6,%7}, {%8,%9}, {%0,%1,%2,%3};"
        : "+f"(c[0]), "+f"(c[1]), "+f"(c[2]), "+f"(c[3])
        : "r"(a[0]), "r"(a[1]), "r"(a[2]), "r"(a[3]), "r"(b[0]), "r"(b[1]));
}
// mma.sync m16n8k16 bf16 (GEMMs + flash PV)
__device__ __forceinline__ void mma16(float* c, const uint32_t* a, const uint32_t* b) {
    asm volatile(
        "mma.sync.aligned.m16n8k16.row.col.f32.bf16.bf16.f32 "
        "{%0,%1,%2,%3}, {%4,%5,%6,%7}, {%8,%9}, {%0,%1,%2,%3};"
        : "+f"(c[0]), "+f"(c[1]), "+f"(c[2]), "+f"(c[3])
        : "r"(a[0]), "r"(a[1]), "r"(a[2]), "r"(a[3]), "r"(b[0]), "r"(b[1]));
}

__device__ __forceinline__ void bf16_split(float v, __nv_bfloat16& h, __nv_bfloat16& l) {
    h = __float2bfloat16(v);
    l = __float2bfloat16(v - __bfloat162float(h));
}

// ---------------- prep kernels ----------------
struct alignas(8) bf16x4 { __nv_bfloat162 a, b; };

__global__ void __launch_bounds__(256) split_kernel(const float* __restrict__ in,
                                                    __nv_bfloat16* __restrict__ hi,
                                                    __nv_bfloat16* __restrict__ lo, int n4) {
    int i = blockIdx.x * blockDim.x + threadIdx.x;
    if (i < n4) {
        float4 v = ((const float4*)in)[i];
        __nv_bfloat16 h0, h1, h2, h3, l0, l1, l2, l3;
        bf16_split(v.x, h0, l0);
        bf16_split(v.y, h1, l1);
        bf16_split(v.z, h2, l2);
        bf16_split(v.w, h3, l3);
        bf16x4 H; H.a = __nv_bfloat162(h0, h1); H.b = __nv_bfloat162(h2, h3);
        bf16x4 L; L.a = __nv_bfloat162(l0, l1); L.b = __nv_bfloat162(l2, l3);
        ((bf16x4*)hi)[i] = H;
        ((bf16x4*)lo)[i] = L;
    }
}

// W [K=1024][N=1024] -> Wt hi/lo [N][K] bf16, 4 matrices via blockIdx.z
__global__ void __launch_bounds__(256) transpose_split_kernel(
    const float* __restrict__ w0, const float* __restrict__ w1,
    const float* __restrict__ w2, const float* __restrict__ w3,
    __nv_bfloat16* __restrict__ hi, __nv_bfloat16* __restrict__ lo)
{
    __shared__ float t[32][33];
    int z = blockIdx.z;
    const float* W = (z == 0) ? w0 : (z == 1) ? w1 : (z == 2) ? w2 : w3;
    __nv_bfloat16* H = hi + (size_t)z * DD * NCOLS;
    __nv_bfloat16* L = lo + (size_t)z * DD * NCOLS;
    int tx = threadIdx.x & 31, ty = threadIdx.x >> 5;
    int n0 = blockIdx.x * 32, k0 = blockIdx.y * 32;
#pragma unroll
    for (int i = 0; i < 4; i++)
        t[ty + i * 8][tx] = W[(size_t)(k0 + ty + i * 8) * NCOLS + n0 + tx];
    __syncthreads();
#pragma unroll
    for (int i = 0; i < 4; i++) {
        float v = t[tx][ty + i * 8];
        __nv_bfloat16 h, l;
        bf16_split(v, h, l);
        size_t o = (size_t)(n0 + ty + i * 8) * DD + k0 + tx;
        H[o] = h;
        L[o] = l;
    }
}

// ---------------- bf16x3 GEMM: tile 128x64, warp 32x32, 2 CTAs/SM ----------------
// D = Ah*Bh + Ah*Bl + Al*Bh
// MODE 0: C=[B,H,S,HD] tf32-rounded f32, (acc+bias)*scale   (Q / K)
// MODE 1: V^T split -> C=bf16 hi, C2=bf16 lo, layout [B,H,HD,S]
// MODE 2: C row-major [M][N] plain fp32 (final output)
#define BK2 32
#define BSTRW 20                   // 32-bit words per smem row
#define ATILE_W (128*BSTRW)        // 2560 words
#define BTILE_W (64*BSTRW)         // 1280 words
#define GEMM_SMEM ((2*2*ATILE_W + 2*2*BTILE_W)*4)   // 61440 bytes

template<int MODE>
__global__ void __launch_bounds__(256, 2) gemm_tc(
    const __nv_bfloat16* __restrict__ Ahi, const __nv_bfloat16* __restrict__ Alo,
    const __nv_bfloat16* __restrict__ Bhi, const __nv_bfloat16* __restrict__ Blo,
    const float* __restrict__ bias, float* __restrict__ C, float* __restrict__ C2,
    int Kdim, float scale)
{
    extern __shared__ uint32_t smw[];
    uint32_t* sAH = smw;                       // [2][ATILE_W]
    uint32_t* sAL = smw + 2 * ATILE_W;
    uint32_t* sBH = smw + 4 * ATILE_W;         // [2][BTILE_W]
    uint32_t* sBL = smw + 4 * ATILE_W + 2 * BTILE_W;
    const uint32_t uAH = smem_u32(sAH), uAL = smem_u32(sAL);
    const uint32_t uBH = smem_u32(sBH), uBL = smem_u32(sBL);

    const int tid = threadIdx.x, lane = tid & 31, wid = tid >> 5;
    const int grp = lane >> 2, qd = lane & 3;
    const int bm = blockIdx.y << 7, bn = blockIdx.x << 6;
    const int wm = (wid >> 1) << 5, wn = (wid & 1) << 5;

    float c[2][4][4];
#pragma unroll
    for (int i = 0; i < 2; i++)
#pragma unroll
        for (int j = 0; j < 4; j++)
#pragma unroll
            for (int r = 0; r < 4; r++) c[i][j][r] = 0.0f;

    const int NKB = Kdim / BK2;

    auto load_stage = [&](int kb, int st) {
        int koff = kb * BK2;
        // A: 128 rows x 32 bf16 = 4 cp16/row/array
#pragma unroll
        for (int i = 0; i < 2; i++) {
            int ch = i * 256 + tid;
            int row = ch >> 2, seg = ch & 3;
            size_t gA = (size_t)(bm + row) * Kdim + koff + seg * 8;
            uint32_t so = (st * ATILE_W + row * BSTRW + seg * 4) * 4;
            cp16(uAH + so, Ahi + gA);
            cp16(uAL + so, Alo + gA);
        }
        // B: 64 rows
        {
            int row = tid >> 2, seg = tid & 3;
            size_t gB = (size_t)(bn + row) * Kdim + koff + seg * 8;
            uint32_t so = (st * BTILE_W + row * BSTRW + seg * 4) * 4;
            cp16(uBH + so, Bhi + gB);
            cp16(uBL + so, Blo + gB);
        }
        cp_commit();
    };

    load_stage(0, 0);
    for (int kb = 0; kb < NKB; kb++) {
        int st = kb & 1;
        if (kb + 1 < NKB) { load_stage(kb + 1, st ^ 1); cp_wait<1>(); }
        else               { cp_wait<0>(); }
        __syncthreads();

        const uint32_t* AH = sAH + st * ATILE_W;
        const uint32_t* AL = sAL + st * ATILE_W;
        const uint32_t* BH = sBH + st * BTILE_W;
        const uint32_t* BL = sBL + st * BTILE_W;

#pragma unroll
        for (int ks = 0; ks < 2; ks++) {
            const int kw = ks * 8 + qd;
            uint32_t ah[2][4], bh[4][2];
#pragma unroll
            for (int mt = 0; mt < 2; mt++) {
                const uint32_t* p = AH + (wm + mt * 16 + grp) * BSTRW + kw;
                ah[mt][0] = p[0];
                ah[mt][1] = p[8 * BSTRW];
                ah[mt][2] = p[4];
                ah[mt][3] = p[8 * BSTRW + 4];
            }
#pragma unroll
            for (int nt = 0; nt < 4; nt++) {
                const uint32_t* p = BH + (wn + nt * 8 + grp) * BSTRW + kw;
                bh[nt][0] = p[0];
                bh[nt][1] = p[4];
            }
#pragma unroll
            for (int mt = 0; mt < 2; mt++)
#pragma unroll
                for (int nt = 0; nt < 4; nt++) mma16(c[mt][nt], ah[mt], bh[nt]);

            // pass 2: ah * bl
            {
                uint32_t bl[4][2];
#pragma unroll
                for (int nt = 0; nt < 4; nt++) {
                    const uint32_t* p = BL + (wn + nt * 8 + grp) * BSTRW + kw;
                    bl[nt][0] = p[0];
                    bl[nt][1] = p[4];
                }
#pragma unroll
                for (int mt = 0; mt < 2; mt++)
#pragma unroll
                    for (int nt = 0; nt < 4; nt++) mma16(c[mt][nt], ah[mt], bl[nt]);
            }
            // pass 3: al * bh
            {
                uint32_t al[2][4];
#pragma unroll
                for (int mt = 0; mt < 2; mt++) {
                    const uint32_t* p = AL + (wm + mt * 16 + grp) * BSTRW + kw;
                    al[mt][0] = p[0];
                    al[mt][1] = p[8 * BSTRW];
                    al[mt][2] = p[4];
                    al[mt][3] = p[8 * BSTRW + 4];
                }
#pragma unroll
                for (int mt = 0; mt < 2; mt++)
#pragma unroll
                    for (int nt = 0; nt < 4; nt++) mma16(c[mt][nt], al[mt], bh[nt]);
            }
        }
        __syncthreads();
    }

    // epilogue
#pragma unroll
    for (int mt = 0; mt < 2; mt++) {
#pragma unroll
        for (int nt = 0; nt < 4; nt++) {
            int n = bn + wn + nt * 8 + 2 * qd;
            float b0v = bias[n], b1v = bias[n + 1];
#pragma unroll
            for (int rr = 0; rr < 2; rr++) {
                int m = bm + wm + mt * 16 + grp + rr * 8;
                float v0 = (c[mt][nt][rr * 2 + 0] + b0v) * scale;
                float v1 = (c[mt][nt][rr * 2 + 1] + b1v) * scale;
                int b_ = m >> 11, s = m & 2047;
                if (MODE == 0) {
                    int h = n >> 6, hd = n & 63;
                    float2 o = make_float2(tf32_rna(v0), tf32_rna(v1));
                    *(float2*)&C[((size_t)(b_ * HH + h) * SS + s) * HDD + hd] = o;
                } else if (MODE == 1) {
                    // V^T [B,H,HD,S] bf16 hi/lo
                    int h = n >> 6, hd = n & 63;
                    __nv_bfloat16* Vh = (__nv_bfloat16*)C;
                    __nv_bfloat16* Vl = (__nv_bfloat16*)C2;
                    size_t off = ((size_t)((b_ * HH + h) * HDD + hd)) * SS + s;
                    __nv_bfloat16 hh0, ll0, hh1, ll1;
                    bf16_split(v0, hh0, ll0);
                    bf16_split(v1, hh1, ll1);
                    Vh[off] = hh0;       Vl[off] = ll0;
                    Vh[off + SS] = hh1;  Vl[off + SS] = ll1;
                } else {
                    *(float2*)&C[(size_t)m * NCOLS + n] = make_float2(v0, v1);
                }
            }
        }
    }
}

// ---------------- flash attention: QK tf32, PV bf16x3 ----------------
// BQ=128, BK=64 keys/iter, 256 threads (8 warps x 16 q-rows).
#define QSTR 68
#define KSTR 68
#define VSTW 36                          // uint32 words per V^T d-row (72 bf16)
#define PSTW 36                          // uint32 words per P row (72 bf16)
#define QOFF 0                           // f32 words: 128*68 = 8704
#define KOFF  (128*QSTR)                 // 8704 (2 stages x 64 x 68)
#define VHOFF (KOFF + 2*64*KSTR)         // 17408 (uint32 words; 2 st x 64 x 36 = 4608)
#define VLOFF (VHOFF + 2*64*VSTW)        // 22016
#define PHOFF (VLOFF + 2*64*VSTW)        // 26624 (128*36 = 4608)
#define PLOFF (PHOFF + 128*PSTW)         // 31232
#define FLASH_WORDS (PLOFF + 128*PSTW)   // 35840
#define FLASH_SMEM (FLASH_WORDS*4)       // 143360 B

__global__ void __launch_bounds__(256) flash_kernel(
    const float* __restrict__ gq, const float* __restrict__ gk,
    const __nv_bfloat16* __restrict__ gvh, const __nv_bfloat16* __restrict__ gvl,
    float* __restrict__ go)
{
    extern __shared__ float smf[];
    uint32_t* smw = (uint32_t*)smf;
    const uint32_t sb = smem_u32(smf);

    const int tid = threadIdx.x, lane = tid & 31, wid = tid >> 5;
    const int grp = lane >> 2, qd = lane & 3;
    const int qt = blockIdx.x;
    const int bh = blockIdx.y;

    const float* Qg = gq  + ((size_t)bh * SS + qt * 128) * HDD;
    const float* Kg = gk  + (size_t)bh * SS * HDD;
    const __nv_bfloat16* Vh = gvh + (size_t)bh * HDD * SS;   // V^T [HD][S]
    const __nv_bfloat16* Vl = gvl + (size_t)bh * HDD * SS;

#pragma unroll
    for (int i = 0; i < 8; i++) {
        int ch = i * 256 + tid;
        int row = ch >> 4, seg = ch & 15;
        cp16(sb + (QOFF + row * QSTR) * 4 + seg * 16, Qg + row * 64 + seg * 4);
    }
    auto load_kv = [&](int kt, int st) {
        // K: 64 rows x 64 f32
#pragma unroll
        for (int i = 0; i < 4; i++) {
            int ch = i * 256 + tid;
            int row = ch >> 4, seg = ch & 15;
            cp16(sb + (KOFF + st * 64 * KSTR + row * KSTR) * 4 + seg * 16,
                 Kg + (size_t)(kt * 64 + row) * 64 + seg * 4);
        }
        // V^T: 64 d-rows x 64 keys bf16 (8 cp16/row/array)
#pragma unroll
        for (int i = 0; i < 2; i++) {
            int ch = i * 256 + tid;
            int row = ch >> 3, seg = ch & 7;
            size_t g = (size_t)row * SS + kt * 64 + seg * 8;
            cp16(sb + (VHOFF + st * 64 * VSTW + row * VSTW + seg * 4) * 4, Vh + g);
            cp16(sb + (VLOFF + st * 64 * VSTW + row * VSTW + seg * 4) * 4, Vl + g);
        }
        cp_commit();
    };
    load_kv(0, 0);

    float co[8][4];
#pragma unroll
    for (int i = 0; i < 8; i++)
#pragma unroll
        for (int r = 0; r < 4; r++) co[i][r] = 0.0f;
    float m0 = -1e30f, m1 = -1e30f, l0 = 0.0f, l1 = 0.0f;

    const int r0 = wid * 16;
    const float* Qw = smf + QOFF + (r0 + grp) * QSTR + qd;
    uint32_t* PhW = smw + PHOFF + (r0 + grp) * PSTW;
    uint32_t* PlW = smw + PLOFF + (r0 + grp) * PSTW;

    for (int kt = 0; kt < SS / 64; kt++) {
        const int st = kt & 1;
        __syncthreads();
        if (kt + 1 < SS / 64) { load_kv(kt + 1, st ^ 1); cp_wait<1>(); }
        else                   { cp_wait<0>(); }
        __syncthreads();

        const float*    Kb  = smf + KOFF + st * 64 * KSTR;
        const uint32_t* VhB = smw + VHOFF + st * 64 * VSTW;
        const uint32_t* VlB = smw + VLOFF + st * 64 * VSTW;

        // ---- S = Q K^T (tf32 single-pass)
        float cs[8][4];
#pragma unroll
        for (int i = 0; i < 8; i++)
#pragma unroll
            for (int r = 0; r < 4; r++) cs[i][r] = 0.0f;
#pragma unroll
        for (int ks = 0; ks < 8; ks++) {
            const int d = ks * 8;
            uint32_t a[4];
            a[0] = f2b(Qw[d]);
            a[1] = f2b(Qw[d + 8 * QSTR]);
            a[2] = f2b(Qw[d + 4]);
            a[3] = f2b(Qw[d + 8 * QSTR + 4]);
#pragma unroll
            for (int nt = 0; nt < 8; nt++) {
                uint32_t b[2];
                const float* p = Kb + (nt * 8 + grp) * KSTR + d + qd;
                b[0] = f2b(p[0]);
                b[1] = f2b(p[4]);
                mma8(cs[nt], a, b);
            }
        }

        // ---- online softmax; P stored bf16 hi/lo packed
        float mx0 = -1e30f, mx1 = -1e30f;
#pragma unroll
        for (int nt = 0; nt < 8; nt++) {
            mx0 = fmaxf(mx0, fmaxf(cs[nt][0], cs[nt][1]));
            mx1 = fmaxf(mx1, fmaxf(cs[nt][2], cs[nt][3]));
        }
        mx0 = fmaxf(mx0, __shfl_xor_sync(0xffffffffu, mx0, 1));
        mx0 = fmaxf(mx0, __shfl_xor_sync(0xffffffffu, mx0, 2));
        mx1 = fmaxf(mx1, __shfl_xor_sync(0xffffffffu, mx1, 1));
        mx1 = fmaxf(mx1, __shfl_xor_sync(0xffffffffu, mx1, 2));
        float mn0 = fmaxf(m0, mx0), mn1 = fmaxf(m1, mx1);
        float al0 = __expf(m0 - mn0), al1 = __expf(m1 - mn1);
        float s0 = 0.0f, s1 = 0.0f;
#pragma unroll
        for (int nt = 0; nt < 8; nt++) {
            float p0 = __expf(cs[nt][0] - mn0);
            float p1 = __expf(cs[nt][1] - mn0);
            float p2 = __expf(cs[nt][2] - mn1);
            float p3 = __expf(cs[nt][3] - mn1);
            s0 += p0 + p1;
            s1 += p2 + p3;
            uint32_t h01 = pack_bf16(p0, p1);
            float r0f = p0 - __uint_as_float(h01 << 16);
            float r1f = p1 - __uint_as_float(h01 & 0xFFFF0000u);
            PhW[nt * 4 + qd] = h01;
            PlW[nt * 4 + qd] = pack_bf16(r0f, r1f);
            uint32_t h23 = pack_bf16(p2, p3);
            float r2f = p2 - __uint_as_float(h23 << 16);
            float r3f = p3 - __uint_as_float(h23 & 0xFFFF0000u);
            PhW[8 * PSTW + nt * 4 + qd] = h23;
            PlW[8 * PSTW + nt * 4 + qd] = pack_bf16(r2f, r3f);
        }
        s0 += __shfl_xor_sync(0xffffffffu, s0, 1);
        s0 += __shfl_xor_sync(0xffffffffu, s0, 2);
        s1 += __shfl_xor_sync(0xffffffffu, s1, 1);
        s1 += __shfl_xor_sync(0xffffffffu, s1, 2);
        l0 = l0 * al0 + s0;
        l1 = l1 * al1 + s1;
        m0 = mn0;
        m1 = mn1;
#pragma unroll
        for (int nt = 0; nt < 8; nt++) {
            co[nt][0] *= al0; co[nt][1] *= al0;
            co[nt][2] *= al1; co[nt][3] *= al1;
        }
        __syncwarp();

        // ---- O += P V  (bf16x3: Ph*Vh + Ph*Vl + Pl*Vh), 4 k16 steps over 64 keys
#pragma unroll
        for (int ks2 = 0; ks2 < 4; ks2++) {
            const int kw = ks2 * 8 + qd;
            uint32_t aH[4], aL[4];
            aH[0] = PhW[kw];
            aH[1] = PhW[8 * PSTW + kw];
            aH[2] = PhW[kw + 4];
            aH[3] = PhW[8 * PSTW + kw + 4];
            aL[0] = PlW[kw];
            aL[1] = PlW[8 * PSTW + kw];
            aL[2] = PlW[kw + 4];
            aL[3] = PlW[8 * PSTW + kw + 4];
#pragma unroll
            for (int nt = 0; nt < 8; nt++) {
                uint32_t b[2];
                const uint32_t* vh = VhB + (nt * 8 + grp) * VSTW + kw;
                b[0] = vh[0];
                b[1] = vh[4];
                mma16(co[nt], aH, b);
                mma16(co[nt], aL, b);
                const uint32_t* vl = VlB + (nt * 8 + grp) * VSTW + kw;
                b[0] = vl[0];
                b[1] = vl[4];
                mma16(co[nt], aH, b);
            }
        }
        __syncwarp();
    }

    const int b_ = bh >> 4;
    const int h  = bh & 15;
    const float inv0 = 1.0f / l0, inv1 = 1.0f / l1;
    const int q0 = qt * 128 + r0 + grp;
#pragma unroll
    for (int nt = 0; nt < 8; nt++) {
        int n = nt * 8 + 2 * qd;
        *(float2*)&go[((size_t)(b_ * SS + q0) * HH + h) * HDD + n] =
            make_float2(co[nt][0] * inv0, co[nt][1] * inv0);
        *(float2*)&go[((size_t)(b_ * SS + q0 + 8) * HH + h) * HDD + n] =
            make_float2(co[nt][2] * inv1, co[nt][3] * inv1);
    }
}

// ---------------------------------------------------------------------------
extern "C" void kernel_launch(void* const* d_in, const int* in_sizes, int n_in,
                              void* d_out, int out_size)
{
    const float* x  = (const float*)d_in[0];
    const float* wq = (const float*)d_in[1];
    const float* bq = (const float*)d_in[2];
    const float* wk = (const float*)d_in[3];
    const float* bk = (const float*)d_in[4];
    const float* wv = (const float*)d_in[5];
    const float* bv = (const float*)d_in[6];
    const float* wo = (const float*)d_in[7];
    const float* bo = (const float*)d_in[8];
    float* out = (float*)d_out;

    float *gq, *gk, *go;
    __nv_bfloat16 *gvh, *gvl, *xhi, *xlo, *ohi, *olo, *wthi, *wtlo;
    cudaGetSymbolAddress((void**)&gq,   g_q);
    cudaGetSymbolAddress((void**)&gk,   g_k);
    cudaGetSymbolAddress((void**)&gvh,  g_vhi);
    cudaGetSymbolAddress((void**)&gvl,  g_vlo);
    cudaGetSymbolAddress((void**)&go,   g_o);
    cudaGetSymbolAddress((void**)&xhi,  g_xhi);
    cudaGetSymbolAddress((void**)&xlo,  g_xlo);
    cudaGetSymbolAddress((void**)&ohi,  g_ohi);
    cudaGetSymbolAddress((void**)&olo,  g_olo);
    cudaGetSymbolAddress((void**)&wthi, g_wthi);
    cudaGetSymbolAddress((void**)&wtlo, g_wtlo);

    cudaFuncSetAttribute(gemm_tc<0>, cudaFuncAttributeMaxDynamicSharedMemorySize, GEMM_SMEM);
    cudaFuncSetAttribute(gemm_tc<1>, cudaFuncAttributeMaxDynamicSharedMemorySize, GEMM_SMEM);
    cudaFuncSetAttribute(gemm_tc<2>, cudaFuncAttributeMaxDynamicSharedMemorySize, GEMM_SMEM);
    cudaFuncSetAttribute(flash_kernel, cudaFuncAttributeMaxDynamicSharedMemorySize, FLASH_SMEM);

    // prep
    split_kernel<<<(MROWS * DD / 4 + 255) / 256, 256>>>(x, xhi, xlo, MROWS * DD / 4);
    transpose_split_kernel<<<dim3(NCOLS / 32, DD / 32, 4), 256>>>(wq, wk, wv, wo, wthi, wtlo);

    dim3 gblk(NCOLS / 64, MROWS / 128);   // (16, 32)
    const size_t WSZ = (size_t)DD * NCOLS;

    gemm_tc<0><<<gblk, 256, GEMM_SMEM>>>(xhi, xlo, wthi + 0 * WSZ, wtlo + 0 * WSZ,
                                         bq, gq, nullptr, DD, 0.125f);
    gemm_tc<0><<<gblk, 256, GEMM_SMEM>>>(xhi, xlo, wthi + 1 * WSZ, wtlo + 1 * WSZ,
                                         bk, gk, nullptr, DD, 1.0f);
    gemm_tc<1><<<gblk, 256, GEMM_SMEM>>>(xhi, xlo, wthi + 2 * WSZ, wtlo + 2 * WSZ,
                                         bv, (float*)gvh, (float*)gvl, DD, 1.0f);

    flash_kernel<<<dim3(SS / 128, BB * HH), 256, FLASH_SMEM>>>(gq, gk, gvh, gvl, go);

    split_kernel<<<(MROWS * NCOLS / 4 + 255) / 256, 256>>>(go, ohi, olo, MROWS * NCOLS / 4);
    gemm_tc<2><<<gblk, 256, GEMM_SMEM>>>(ohi, olo, wthi + 3 * WSZ, wtlo + 3 * WSZ,
                                         bo, out, nullptr, NCOLS, 1.0f);
}